// round 6
// baseline (speedup 1.0000x reference)
#include <cuda_runtime.h>

#define NV (128*128*128)          // 2097152 voxels
#define SLOPE 0.01f
#define EPSBN 1e-5f

// ---------------- persistent device scratch (no allocations allowed) --------
__device__ float g_bufA[16 * NV];   // 128 MB ping
__device__ float g_bufB[16 * NV];   // 128 MB pong
__device__ float g_stats[5 * 32];   // per layer: [0..15]=sum, [16..31]=sumsq
__device__ float g_n;               // active voxel count

// ---------------- f32x2 helpers (SASS FFMA2 path) ---------------------------
typedef unsigned long long u64;

__device__ __forceinline__ u64 fpack(float lo, float hi) {
    u64 d; asm("mov.b64 %0, {%1, %2};" : "=l"(d) : "f"(lo), "f"(hi)); return d;
}
__device__ __forceinline__ void funpack(u64 d, float& lo, float& hi) {
    asm("mov.b64 {%0, %1}, %2;" : "=f"(lo), "=f"(hi) : "l"(d));
}
__device__ __forceinline__ u64 ffma2(u64 a, u64 b, u64 c) {
    u64 d; asm("fma.rn.f32x2 %0, %1, %2, %3;" : "=l"(d) : "l"(a), "l"(b), "l"(c)); return d;
}

// ---------------- stats zeroing ---------------------------------------------
__global__ void k_zero(float* __restrict__ stats, float* __restrict__ nptr) {
    int t = threadIdx.x;
    if (t < 160) stats[t] = 0.f;
    if (t == 160) *nptr = 0.f;
}

// ---------------- layer 0: 1x1 conv 4->16, masked, + stats + maskf out ------
__global__ __launch_bounds__(256)
void k_layer0(const float* __restrict__ feat, const int* __restrict__ mask,
              const float* __restrict__ w0, const float* __restrict__ b0,
              float* __restrict__ outA, float* __restrict__ maskOut,
              float* __restrict__ statsOut, float* __restrict__ nOut)
{
    __shared__ float ws[64];   // ws[ci*16+co]
    __shared__ float bs[16];
    __shared__ float red[33];
    const int tid = threadIdx.x;
    if (tid < 64) { int co = tid >> 2, ci = tid & 3; ws[ci * 16 + co] = w0[co * 4 + ci]; }
    if (tid < 16) bs[tid] = b0[tid];
    if (tid < 33) red[tid] = 0.f;
    __syncthreads();

    const int v = (blockIdx.x * 256 + tid) * 4;
    const int4 m4 = *(const int4*)(mask + v);
    const float4 mf = make_float4(m4.x > 0 ? 1.f : 0.f, m4.y > 0 ? 1.f : 0.f,
                                  m4.z > 0 ? 1.f : 0.f, m4.w > 0 ? 1.f : 0.f);
    *(float4*)(maskOut + v) = mf;

    float4 acc[16];
    #pragma unroll
    for (int co = 0; co < 16; co++) acc[co] = make_float4(bs[co], bs[co], bs[co], bs[co]);
    #pragma unroll
    for (int ci = 0; ci < 4; ci++) {
        const float4 x = *(const float4*)(feat + ci * NV + v);
        #pragma unroll
        for (int co = 0; co < 16; co++) {
            const float wv = ws[ci * 16 + co];
            acc[co].x += wv * x.x; acc[co].y += wv * x.y;
            acc[co].z += wv * x.z; acc[co].w += wv * x.w;
        }
    }
    float s[16], q[16];
    #pragma unroll
    for (int co = 0; co < 16; co++) {
        const float4 o = make_float4(acc[co].x * mf.x, acc[co].y * mf.y,
                                     acc[co].z * mf.z, acc[co].w * mf.w);
        *(float4*)(outA + co * NV + v) = o;
        s[co] = o.x + o.y + o.z + o.w;
        q[co] = o.x * o.x + o.y * o.y + o.z * o.z + o.w * o.w;
    }
    float cnt = mf.x + mf.y + mf.z + mf.w;
    #pragma unroll
    for (int off = 16; off; off >>= 1) {
        cnt += __shfl_xor_sync(0xffffffffu, cnt, off);
        #pragma unroll
        for (int co = 0; co < 16; co++) {
            s[co] += __shfl_xor_sync(0xffffffffu, s[co], off);
            q[co] += __shfl_xor_sync(0xffffffffu, q[co], off);
        }
    }
    if ((tid & 31) == 0) {
        #pragma unroll
        for (int co = 0; co < 16; co++) {
            atomicAdd(&red[co], s[co]);
            atomicAdd(&red[16 + co], q[co]);
        }
        atomicAdd(&red[32], cnt);
    }
    __syncthreads();
    if (tid < 32) atomicAdd(&statsOut[tid], red[tid]);
    if (tid == 32) atomicAdd(nOut, red[32]);
}

// ---------------- 3x3x3 subm conv 16->16 with fused input BN+LeakyReLU ------
// block: 128 threads; output tile 16(X) x 8(Y) x 4(Z); each thread:
//   8 output channels as 4 f32x2 co-pairs x 8 voxels along X (scalar)
__global__ __launch_bounds__(128)
void k_conv3(const float* __restrict__ inBuf, float* __restrict__ outBuf,
             const int* __restrict__ mask,
             const float* __restrict__ w, const float* __restrict__ bias,
             const float* __restrict__ gam, const float* __restrict__ bet,
             const float* __restrict__ statsIn, float* __restrict__ statsOut,
             const float* __restrict__ nPtr)
{
    __shared__ __align__(16) float s_in[4 * 6 * 10 * 18]; // [ci_local][z:6][y:10][x:18]
    __shared__ __align__(16) float s_w[16 * 27 * 16];     // [(ci*27 + tap)*16 + co]
    __shared__ float s_sc[16], s_sh[16], s_b[16];

    const int tid = threadIdx.x;
    // stage weights (transposed so co is innermost -> adjacent co pairs)
    for (int i = tid; i < 6912; i += 128) {
        const int ci = i / 432;
        const int r  = i - ci * 432;
        const int t  = r >> 4;
        const int co = r & 15;
        s_w[i] = w[(co * 16 + ci) * 27 + t];
    }
    // BN scale/shift of the PREVIOUS layer from its global stats
    if (tid < 16) {
        const float n    = *nPtr;
        const float mean = statsIn[tid] / n;
        const float var  = statsIn[16 + tid] / n - mean * mean;
        const float inv  = rsqrtf(var + EPSBN);
        const float sc   = gam[tid] * inv;
        s_sc[tid] = sc;
        s_sh[tid] = bet[tid] - mean * sc;
        s_b[tid]  = bias[tid];
    }

    const int tx = tid & 1;
    const int ty = (tid >> 1) & 7;
    const int tz = (tid >> 4) & 3;
    const int cog = tid >> 6;
    const int X0 = blockIdx.x * 16, Y0 = blockIdx.y * 8, Z0 = blockIdx.z * 4;

    u64 acc[4][8];    // [co_pair][voxel_x]
    #pragma unroll
    for (int p = 0; p < 4; p++)
        #pragma unroll
        for (int j = 0; j < 8; j++) acc[p][j] = 0ull;

    #pragma unroll 1
    for (int cc = 0; cc < 4; cc++) {        // 4 input-channel chunks of 4
        __syncthreads();
        // fill halo tile for channels [cc*4, cc*4+4) with BN+LeakyReLU applied
        for (int i = tid; i < 4320; i += 128) {
            const int cl   = i / 1080;
            const int site = i - cl * 1080;
            const int z  = site / 180;
            const int r2 = site - z * 180;
            const int y  = r2 / 18;
            const int x  = r2 - y * 18;
            const int gz = Z0 + z - 1, gy = Y0 + y - 1, gx = X0 + x - 1;
            float val = 0.f;
            if (((unsigned)gz < 128u) & ((unsigned)gy < 128u) & ((unsigned)gx < 128u)) {
                const int gv = (gz * 128 + gy) * 128 + gx;
                if (mask[gv] > 0) {
                    const int ci = cc * 4 + cl;
                    const float a = s_sc[ci] * inBuf[ci * NV + gv] + s_sh[ci];
                    val = (a >= 0.f) ? a : SLOPE * a;
                }
            }
            s_in[i] = val;
        }
        __syncthreads();

        #pragma unroll 1
        for (int cl = 0; cl < 4; cl++) {
            const int ci = cc * 4 + cl;
            const float* wci = s_w + ci * 432 + cog * 8;
            #pragma unroll
            for (int kz = 0; kz < 3; kz++) {
                #pragma unroll
                for (int ky = 0; ky < 3; ky++) {
                    const float* rowp = s_in +
                        ((cl * 6 + tz + kz) * 10 + ty + ky) * 18 + tx * 8;
                    float2 vv[5];
                    #pragma unroll
                    for (int i2 = 0; i2 < 5; i2++) vv[i2] = ((const float2*)rowp)[i2];
                    u64 dup[10];    // (v, v) duplicated voxel values, x offsets 0..9
                    #pragma unroll
                    for (int i2 = 0; i2 < 5; i2++) {
                        dup[2 * i2]     = fpack(vv[i2].x, vv[i2].x);
                        dup[2 * i2 + 1] = fpack(vv[i2].y, vv[i2].y);
                    }
                    const float* wrow = wci + (kz * 3 + ky) * 48;
                    #pragma unroll
                    for (int kx = 0; kx < 3; kx++) {
                        u64 wp[4];
                        #pragma unroll
                        for (int p = 0; p < 4; p++)
                            wp[p] = *(const u64*)(wrow + kx * 16 + 2 * p);
                        #pragma unroll
                        for (int p = 0; p < 4; p++)
                            #pragma unroll
                            for (int j = 0; j < 8; j++)
                                acc[p][j] = ffma2(dup[j + kx], wp[p], acc[p][j]);
                    }
                }
            }
        }
    }

    // ---- epilogue: bias, mask, store raw, accumulate this layer's stats ----
    const int oz = Z0 + tz, oy = Y0 + ty, ox = X0 + tx * 8;
    const int base = (oz * 128 + oy) * 128 + ox;
    const int4 ma = *(const int4*)(mask + base);
    const int4 mb = *(const int4*)(mask + base + 4);
    const float mm[8] = { ma.x > 0 ? 1.f : 0.f, ma.y > 0 ? 1.f : 0.f,
                          ma.z > 0 ? 1.f : 0.f, ma.w > 0 ? 1.f : 0.f,
                          mb.x > 0 ? 1.f : 0.f, mb.y > 0 ? 1.f : 0.f,
                          mb.z > 0 ? 1.f : 0.f, mb.w > 0 ? 1.f : 0.f };
    float o[8][8];    // [co_local][voxel]
    #pragma unroll
    for (int p = 0; p < 4; p++)
        #pragma unroll
        for (int j = 0; j < 8; j++)
            funpack(acc[p][j], o[2 * p][j], o[2 * p + 1][j]);

    float ssum[8], ssq[8];
    #pragma unroll
    for (int co = 0; co < 8; co++) {
        const int c = cog * 8 + co;
        const float bb = s_b[c];
        float s = 0.f, q = 0.f;
        #pragma unroll
        for (int j = 0; j < 8; j++) {
            const float val = (o[co][j] + bb) * mm[j];
            o[co][j] = val; s += val; q += val * val;
        }
        *(float4*)(outBuf + c * NV + base) =
            make_float4(o[co][0], o[co][1], o[co][2], o[co][3]);
        *(float4*)(outBuf + c * NV + base + 4) =
            make_float4(o[co][4], o[co][5], o[co][6], o[co][7]);
        ssum[co] = s; ssq[co] = q;
    }
    #pragma unroll
    for (int off = 16; off; off >>= 1) {
        #pragma unroll
        for (int co = 0; co < 8; co++) {
            ssum[co] += __shfl_xor_sync(0xffffffffu, ssum[co], off);
            ssq[co]  += __shfl_xor_sync(0xffffffffu, ssq[co],  off);
        }
    }
    if ((tid & 31) == 0) {
        #pragma unroll
        for (int co = 0; co < 8; co++) {
            const int c = cog * 8 + co;
            atomicAdd(&statsOut[c], ssum[co]);
            atomicAdd(&statsOut[16 + c], ssq[co]);
        }
    }
}

// ---------------- layer 5: BN4+act then 1x1 conv 16->16, masked, to d_out ---
__global__ __launch_bounds__(256)
void k_layer5(const float* __restrict__ inBuf, const int* __restrict__ mask,
              const float* __restrict__ w5, const float* __restrict__ b5,
              const float* __restrict__ gam, const float* __restrict__ bet,
              const float* __restrict__ statsIn, const float* __restrict__ nPtr,
              float* __restrict__ out)
{
    __shared__ float ws[256];                 // ws[ci*16+co]
    __shared__ float s_sc[16], s_sh[16], s_b[16];
    const int tid = threadIdx.x;
    { const int ci = tid >> 4, co = tid & 15; ws[tid] = w5[co * 16 + ci]; }
    if (tid < 16) {
        const float n    = *nPtr;
        const float mean = statsIn[tid] / n;
        const float var  = statsIn[16 + tid] / n - mean * mean;
        const float inv  = rsqrtf(var + EPSBN);
        const float sc   = gam[tid] * inv;
        s_sc[tid] = sc;
        s_sh[tid] = bet[tid] - mean * sc;
        s_b[tid]  = b5[tid];
    }
    __syncthreads();

    const int v = (blockIdx.x * 256 + tid) * 4;
    const int4 m4 = *(const int4*)(mask + v);
    const float4 mf = make_float4(m4.x > 0 ? 1.f : 0.f, m4.y > 0 ? 1.f : 0.f,
                                  m4.z > 0 ? 1.f : 0.f, m4.w > 0 ? 1.f : 0.f);
    float4 acc[16];
    #pragma unroll
    for (int co = 0; co < 16; co++) acc[co] = make_float4(0.f, 0.f, 0.f, 0.f);
    #pragma unroll
    for (int ci = 0; ci < 16; ci++) {
        const float4 a = *(const float4*)(inBuf + ci * NV + v);
        const float sc = s_sc[ci], sh = s_sh[ci];
        float4 t;
        t.x = sc * a.x + sh; t.y = sc * a.y + sh;
        t.z = sc * a.z + sh; t.w = sc * a.w + sh;
        t.x = ((t.x >= 0.f) ? t.x : SLOPE * t.x) * mf.x;
        t.y = ((t.y >= 0.f) ? t.y : SLOPE * t.y) * mf.y;
        t.z = ((t.z >= 0.f) ? t.z : SLOPE * t.z) * mf.z;
        t.w = ((t.w >= 0.f) ? t.w : SLOPE * t.w) * mf.w;
        #pragma unroll
        for (int co = 0; co < 16; co++) {
            const float wv = ws[ci * 16 + co];
            acc[co].x += wv * t.x; acc[co].y += wv * t.y;
            acc[co].z += wv * t.z; acc[co].w += wv * t.w;
        }
    }
    #pragma unroll
    for (int co = 0; co < 16; co++) {
        const float bb = s_b[co];
        const float4 o = make_float4((acc[co].x + bb) * mf.x, (acc[co].y + bb) * mf.y,
                                     (acc[co].z + bb) * mf.z, (acc[co].w + bb) * mf.w);
        *(float4*)(out + co * NV + v) = o;
    }
}

// ---------------- host launcher ---------------------------------------------
extern "C" void kernel_launch(void* const* d_in, const int* in_sizes, int n_in,
                              void* d_out, int out_size)
{
    (void)in_sizes; (void)n_in; (void)out_size;
    const float* feat = (const float*)d_in[0];
    const int*   mask = (const int*)d_in[1];
    const float* w0  = (const float*)d_in[2];
    const float* b0  = (const float*)d_in[3];
    const float* g0  = (const float*)d_in[4];
    const float* be0 = (const float*)d_in[5];
    const float *wL[4], *bL[4], *gL[4], *beL[4];
    for (int i = 0; i < 4; i++) {
        wL[i]  = (const float*)d_in[6 + 4 * i];
        bL[i]  = (const float*)d_in[7 + 4 * i];
        gL[i]  = (const float*)d_in[8 + 4 * i];
        beL[i] = (const float*)d_in[9 + 4 * i];
    }
    const float* w5 = (const float*)d_in[22];
    const float* b5 = (const float*)d_in[23];
    float* out = (float*)d_out;

    float *bufA, *bufB, *stats, *nptr;
    cudaGetSymbolAddress((void**)&bufA,  g_bufA);
    cudaGetSymbolAddress((void**)&bufB,  g_bufB);
    cudaGetSymbolAddress((void**)&stats, g_stats);
    cudaGetSymbolAddress((void**)&nptr,  g_n);

    k_zero<<<1, 192>>>(stats, nptr);
    // layer 0 + maskf output (y occupies first 16*NV floats of d_out)
    k_layer0<<<2048, 256>>>(feat, mask, w0, b0, bufA, out + 16 * NV, stats, nptr);

    const dim3 grid(8, 16, 32);
    float* pin = bufA;
    float* pout = bufB;
    for (int l = 0; l < 4; l++) {
        const float* gprev  = (l == 0) ? g0  : gL[l - 1];
        const float* beprev = (l == 0) ? be0 : beL[l - 1];
        k_conv3<<<grid, 128>>>(pin, pout, mask, wL[l], bL[l],
                               gprev, beprev,
                               stats + 32 * l, stats + 32 * (l + 1), nptr);
        float* t = pin; pin = pout; pout = t;
    }
    k_layer5<<<2048, 256>>>(pin, mask, w5, b5, gL[3], beL[3],
                            stats + 32 * 4, nptr, out);
}

// round 12
// speedup vs baseline: 1.3902x; 1.3902x over previous
#include <cuda_runtime.h>

#define NV (128*128*128)          // 2097152 voxels
#define SLOPE 0.01f
#define EPSBN 1e-5f

// ---------------- persistent device scratch (no allocations allowed) --------
__device__ float g_bufA[16 * NV];   // 128 MB raw ping
__device__ float g_bufB[16 * NV];   // 128 MB raw pong
__device__ float g_bufC[16 * NV];   // 128 MB activated input
__device__ float g_stats[5 * 32];   // per layer: [0..15]=sum, [16..31]=sumsq
__device__ float g_n;               // active voxel count

// ---------------- f32x2 helpers (SASS FFMA2 path) ---------------------------
typedef unsigned long long u64;

__device__ __forceinline__ u64 fpack(float lo, float hi) {
    u64 d; asm("mov.b64 %0, {%1, %2};" : "=l"(d) : "f"(lo), "f"(hi)); return d;
}
__device__ __forceinline__ void funpack(u64 d, float& lo, float& hi) {
    asm("mov.b64 {%0, %1}, %2;" : "=f"(lo), "=f"(hi) : "l"(d));
}
__device__ __forceinline__ u64 ffma2(u64 a, u64 b, u64 c) {
    u64 d; asm("fma.rn.f32x2 %0, %1, %2, %3;" : "=l"(d) : "l"(a), "l"(b), "l"(c)); return d;
}
__device__ __forceinline__ unsigned smaddr(const void* p) {
    return (unsigned)__cvta_generic_to_shared(p);
}
__device__ __forceinline__ void cpa4(unsigned dst, const void* src, unsigned sz) {
    asm volatile("cp.async.ca.shared.global [%0], [%1], 4, %2;"
                 :: "r"(dst), "l"(src), "r"(sz));
}

// ---------------- stats zeroing ---------------------------------------------
__global__ void k_zero(float* __restrict__ stats, float* __restrict__ nptr) {
    int t = threadIdx.x;
    if (t < 160) stats[t] = 0.f;
    if (t == 160) *nptr = 0.f;
}

// ---------------- layer 0: 1x1 conv 4->16, masked, + stats + maskf out ------
__global__ __launch_bounds__(256)
void k_layer0(const float* __restrict__ feat, const int* __restrict__ mask,
              const float* __restrict__ w0, const float* __restrict__ b0,
              float* __restrict__ outA, float* __restrict__ maskOut,
              float* __restrict__ statsOut, float* __restrict__ nOut)
{
    __shared__ float ws[64];   // ws[ci*16+co]
    __shared__ float bs[16];
    __shared__ float red[33];
    const int tid = threadIdx.x;
    if (tid < 64) { int co = tid >> 2, ci = tid & 3; ws[ci * 16 + co] = w0[co * 4 + ci]; }
    if (tid < 16) bs[tid] = b0[tid];
    if (tid < 33) red[tid] = 0.f;
    __syncthreads();

    const int v = (blockIdx.x * 256 + tid) * 4;
    const int4 m4 = *(const int4*)(mask + v);
    const float4 mf = make_float4(m4.x > 0 ? 1.f : 0.f, m4.y > 0 ? 1.f : 0.f,
                                  m4.z > 0 ? 1.f : 0.f, m4.w > 0 ? 1.f : 0.f);
    *(float4*)(maskOut + v) = mf;

    float4 acc[16];
    #pragma unroll
    for (int co = 0; co < 16; co++) acc[co] = make_float4(bs[co], bs[co], bs[co], bs[co]);
    #pragma unroll
    for (int ci = 0; ci < 4; ci++) {
        const float4 x = *(const float4*)(feat + ci * NV + v);
        #pragma unroll
        for (int co = 0; co < 16; co++) {
            const float wv = ws[ci * 16 + co];
            acc[co].x += wv * x.x; acc[co].y += wv * x.y;
            acc[co].z += wv * x.z; acc[co].w += wv * x.w;
        }
    }
    float s[16], q[16];
    #pragma unroll
    for (int co = 0; co < 16; co++) {
        const float4 o = make_float4(acc[co].x * mf.x, acc[co].y * mf.y,
                                     acc[co].z * mf.z, acc[co].w * mf.w);
        *(float4*)(outA + co * NV + v) = o;
        s[co] = o.x + o.y + o.z + o.w;
        q[co] = o.x * o.x + o.y * o.y + o.z * o.z + o.w * o.w;
    }
    float cnt = mf.x + mf.y + mf.z + mf.w;
    #pragma unroll
    for (int off = 16; off; off >>= 1) {
        cnt += __shfl_xor_sync(0xffffffffu, cnt, off);
        #pragma unroll
        for (int co = 0; co < 16; co++) {
            s[co] += __shfl_xor_sync(0xffffffffu, s[co], off);
            q[co] += __shfl_xor_sync(0xffffffffu, q[co], off);
        }
    }
    if ((tid & 31) == 0) {
        #pragma unroll
        for (int co = 0; co < 16; co++) {
            atomicAdd(&red[co], s[co]);
            atomicAdd(&red[16 + co], q[co]);
        }
        atomicAdd(&red[32], cnt);
    }
    __syncthreads();
    if (tid < 32) atomicAdd(&statsOut[tid], red[tid]);
    if (tid == 32) atomicAdd(nOut, red[32]);
}

// ---------------- BN + LeakyReLU pass: raw -> activated (masked) ------------
__global__ __launch_bounds__(256)
void k_bnact(const float* __restrict__ raw, const int* __restrict__ mask,
             const float* __restrict__ gam, const float* __restrict__ bet,
             const float* __restrict__ statsIn, const float* __restrict__ nPtr,
             float* __restrict__ act)
{
    __shared__ float s_sc[16], s_sh[16];
    const int tid = threadIdx.x;
    if (tid < 16) {
        const float n    = *nPtr;
        const float mean = statsIn[tid] / n;
        const float var  = statsIn[16 + tid] / n - mean * mean;
        const float inv  = rsqrtf(var + EPSBN);
        const float sc   = gam[tid] * inv;
        s_sc[tid] = sc;
        s_sh[tid] = bet[tid] - mean * sc;
    }
    __syncthreads();

    const int v = (blockIdx.x * 256 + tid) * 4;
    const int4 m4 = *(const int4*)(mask + v);
    const float4 mf = make_float4(m4.x > 0 ? 1.f : 0.f, m4.y > 0 ? 1.f : 0.f,
                                  m4.z > 0 ? 1.f : 0.f, m4.w > 0 ? 1.f : 0.f);
    #pragma unroll
    for (int ci = 0; ci < 16; ci++) {
        const float4 a = *(const float4*)(raw + ci * NV + v);
        const float sc = s_sc[ci], sh = s_sh[ci];
        float4 t;
        t.x = sc * a.x + sh; t.y = sc * a.y + sh;
        t.z = sc * a.z + sh; t.w = sc * a.w + sh;
        t.x = ((t.x >= 0.f) ? t.x : SLOPE * t.x) * mf.x;
        t.y = ((t.y >= 0.f) ? t.y : SLOPE * t.y) * mf.y;
        t.z = ((t.z >= 0.f) ? t.z : SLOPE * t.z) * mf.z;
        t.w = ((t.w >= 0.f) ? t.w : SLOPE * t.w) * mf.w;
        *(float4*)(act + ci * NV + v) = t;
    }
}

// ---------------- 3x3x3 subm conv 16->16 on preactivated input --------------
// block: 256 threads; output tile 16(X) x 8(Y) x 4(Z); each thread:
//   8 output channels as 4 f32x2 co-pairs x 4 voxels along X
// cp.async double-buffered fills (input tile + per-chunk weights)
__global__ __launch_bounds__(256, 3)
void k_conv3(const float* __restrict__ act, float* __restrict__ outBuf,
             const int* __restrict__ mask,
             const float* __restrict__ w, const float* __restrict__ bias,
             float* __restrict__ statsOut)
{
    __shared__ __align__(16) float s_in[2][4320];  // [buf][ci4:4][z:6][y:10][x:18]
    __shared__ __align__(16) float s_w[2][1728];   // [buf][(cl*27 + tap)*16 + co]
    __shared__ float s_red[32];
    __shared__ float s_b[16];

    const int tid = threadIdx.x;
    if (tid < 32) s_red[tid] = 0.f;
    if (tid < 16) s_b[tid] = bias[tid];

    const int tx  = tid & 3;
    const int ty  = (tid >> 2) & 7;
    const int tz  = (tid >> 5) & 3;
    const int cog = tid >> 7;
    const int X0 = blockIdx.x * 16, Y0 = blockIdx.y * 8, Z0 = blockIdx.z * 4;

    auto fill = [&](int cc, int b) {
        // input tile (halo, zero-filled out of range; act already has BN+LReLU+mask)
        for (int i = tid; i < 4320; i += 256) {
            const int cl = i / 1080;
            const int r  = i - cl * 1080;
            const int z  = r / 180;
            const int r2 = r - z * 180;
            const int y  = r2 / 18;
            const int x  = r2 - y * 18;
            const int gz = Z0 + z - 1, gy = Y0 + y - 1, gx = X0 + x - 1;
            const bool ok = ((unsigned)gz < 128u) & ((unsigned)gy < 128u) & ((unsigned)gx < 128u);
            const int gv = ok ? ((gz * 128 + gy) * 128 + gx) : 0;
            const float* src = ok ? (act + (cc * 4 + cl) * NV + gv) : act;
            cpa4(smaddr(&s_in[b][i]), src, ok ? 4u : 0u);
        }
        // weights for this chunk, transposed so co is innermost
        for (int i = tid; i < 1728; i += 256) {
            const int cl = i / 432;
            const int r  = i - cl * 432;
            const int t  = r >> 4;
            const int co = r & 15;
            cpa4(smaddr(&s_w[b][i]), w + (co * 16 + cc * 4 + cl) * 27 + t, 4u);
        }
        asm volatile("cp.async.commit_group;" ::: "memory");
    };

    u64 acc[4][4];    // [co_pair][voxel_x]
    #pragma unroll
    for (int p = 0; p < 4; p++)
        #pragma unroll
        for (int j = 0; j < 4; j++) acc[p][j] = 0ull;

    fill(0, 0);

    #pragma unroll 1
    for (int cc = 0; cc < 4; cc++) {        // 4 input-channel chunks of 4
        const int b = cc & 1;
        if (cc < 3) {
            fill(cc + 1, b ^ 1);
            asm volatile("cp.async.wait_group 1;" ::: "memory");
        } else {
            asm volatile("cp.async.wait_group 0;" ::: "memory");
        }
        __syncthreads();

        #pragma unroll 1
        for (int cl = 0; cl < 4; cl++) {
            const float* wci = s_w[b] + cl * 432 + cog * 8;
            #pragma unroll
            for (int kz = 0; kz < 3; kz++) {
                #pragma unroll
                for (int ky = 0; ky < 3; ky++) {
                    const float* rowp = s_in[b] +
                        ((cl * 6 + tz + kz) * 10 + ty + ky) * 18 + tx * 4;
                    const float2 v0 = ((const float2*)rowp)[0];
                    const float2 v1 = ((const float2*)rowp)[1];
                    const float2 v2 = ((const float2*)rowp)[2];
                    u64 dup[6];
                    dup[0] = fpack(v0.x, v0.x); dup[1] = fpack(v0.y, v0.y);
                    dup[2] = fpack(v1.x, v1.x); dup[3] = fpack(v1.y, v1.y);
                    dup[4] = fpack(v2.x, v2.x); dup[5] = fpack(v2.y, v2.y);
                    const float* wrow = wci + (kz * 3 + ky) * 48;
                    #pragma unroll
                    for (int kx = 0; kx < 3; kx++) {
                        u64 wp[4];
                        #pragma unroll
                        for (int p = 0; p < 4; p++)
                            wp[p] = *(const u64*)(wrow + kx * 16 + 2 * p);
                        #pragma unroll
                        for (int p = 0; p < 4; p++)
                            #pragma unroll
                            for (int j = 0; j < 4; j++)
                                acc[p][j] = ffma2(dup[j + kx], wp[p], acc[p][j]);
                    }
                }
            }
        }
        __syncthreads();
    }

    // ---- epilogue: bias, mask, store raw, accumulate this layer's stats ----
    const int oz = Z0 + tz, oy = Y0 + ty, ox = X0 + tx * 4;
    const int base = (oz * 128 + oy) * 128 + ox;
    const int4 m4 = *(const int4*)(mask + base);
    const float mm[4] = { m4.x > 0 ? 1.f : 0.f, m4.y > 0 ? 1.f : 0.f,
                          m4.z > 0 ? 1.f : 0.f, m4.w > 0 ? 1.f : 0.f };
    float o[8][4];
    #pragma unroll
    for (int p = 0; p < 4; p++)
        #pragma unroll
        for (int j = 0; j < 4; j++)
            funpack(acc[p][j], o[2 * p][j], o[2 * p + 1][j]);

    float ssum[8], ssq[8];
    #pragma unroll
    for (int co = 0; co < 8; co++) {
        const int c = cog * 8 + co;
        const float bb = s_b[c];
        float s = 0.f, q = 0.f;
        #pragma unroll
        for (int j = 0; j < 4; j++) {
            const float val = (o[co][j] + bb) * mm[j];
            o[co][j] = val; s += val; q += val * val;
        }
        *(float4*)(outBuf + c * NV + base) =
            make_float4(o[co][0], o[co][1], o[co][2], o[co][3]);
        ssum[co] = s; ssq[co] = q;
    }
    #pragma unroll
    for (int off = 16; off; off >>= 1) {
        #pragma unroll
        for (int co = 0; co < 8; co++) {
            ssum[co] += __shfl_xor_sync(0xffffffffu, ssum[co], off);
            ssq[co]  += __shfl_xor_sync(0xffffffffu, ssq[co],  off);
        }
    }
    if ((tid & 31) == 0) {
        #pragma unroll
        for (int co = 0; co < 8; co++) {
            const int c = cog * 8 + co;
            atomicAdd(&s_red[c], ssum[co]);
            atomicAdd(&s_red[16 + c], ssq[co]);
        }
    }
    __syncthreads();
    if (tid < 32) atomicAdd(&statsOut[tid], s_red[tid]);
}

// ---------------- layer 5: BN4+act then 1x1 conv 16->16, masked, to d_out ---
__global__ __launch_bounds__(256)
void k_layer5(const float* __restrict__ inBuf, const int* __restrict__ mask,
              const float* __restrict__ w5, const float* __restrict__ b5,
              const float* __restrict__ gam, const float* __restrict__ bet,
              const float* __restrict__ statsIn, const float* __restrict__ nPtr,
              float* __restrict__ out)
{
    __shared__ float ws[256];                 // ws[ci*16+co]
    __shared__ float s_sc[16], s_sh[16], s_b[16];
    const int tid = threadIdx.x;
    { const int ci = tid >> 4, co = tid & 15; ws[tid] = w5[co * 16 + ci]; }
    if (tid < 16) {
        const float n    = *nPtr;
        const float mean = statsIn[tid] / n;
        const float var  = statsIn[16 + tid] / n - mean * mean;
        const float inv  = rsqrtf(var + EPSBN);
        const float sc   = gam[tid] * inv;
        s_sc[tid] = sc;
        s_sh[tid] = bet[tid] - mean * sc;
        s_b[tid]  = b5[tid];
    }
    __syncthreads();

    const int v = (blockIdx.x * 256 + tid) * 4;
    const int4 m4 = *(const int4*)(mask + v);
    const float4 mf = make_float4(m4.x > 0 ? 1.f : 0.f, m4.y > 0 ? 1.f : 0.f,
                                  m4.z > 0 ? 1.f : 0.f, m4.w > 0 ? 1.f : 0.f);
    float4 acc[16];
    #pragma unroll
    for (int co = 0; co < 16; co++) acc[co] = make_float4(0.f, 0.f, 0.f, 0.f);
    #pragma unroll
    for (int ci = 0; ci < 16; ci++) {
        const float4 a = *(const float4*)(inBuf + ci * NV + v);
        const float sc = s_sc[ci], sh = s_sh[ci];
        float4 t;
        t.x = sc * a.x + sh; t.y = sc * a.y + sh;
        t.z = sc * a.z + sh; t.w = sc * a.w + sh;
        t.x = ((t.x >= 0.f) ? t.x : SLOPE * t.x) * mf.x;
        t.y = ((t.y >= 0.f) ? t.y : SLOPE * t.y) * mf.y;
        t.z = ((t.z >= 0.f) ? t.z : SLOPE * t.z) * mf.z;
        t.w = ((t.w >= 0.f) ? t.w : SLOPE * t.w) * mf.w;
        #pragma unroll
        for (int co = 0; co < 16; co++) {
            const float wv = ws[ci * 16 + co];
            acc[co].x += wv * t.x; acc[co].y += wv * t.y;
            acc[co].z += wv * t.z; acc[co].w += wv * t.w;
        }
    }
    #pragma unroll
    for (int co = 0; co < 16; co++) {
        const float bb = s_b[co];
        const float4 o = make_float4((acc[co].x + bb) * mf.x, (acc[co].y + bb) * mf.y,
                                     (acc[co].z + bb) * mf.z, (acc[co].w + bb) * mf.w);
        *(float4*)(out + co * NV + v) = o;
    }
}

// ---------------- host launcher ---------------------------------------------
extern "C" void kernel_launch(void* const* d_in, const int* in_sizes, int n_in,
                              void* d_out, int out_size)
{
    (void)in_sizes; (void)n_in; (void)out_size;
    const float* feat = (const float*)d_in[0];
    const int*   mask = (const int*)d_in[1];
    const float* w0  = (const float*)d_in[2];
    const float* b0  = (const float*)d_in[3];
    const float* g0  = (const float*)d_in[4];
    const float* be0 = (const float*)d_in[5];
    const float *wL[4], *bL[4], *gL[4], *beL[4];
    for (int i = 0; i < 4; i++) {
        wL[i]  = (const float*)d_in[6 + 4 * i];
        bL[i]  = (const float*)d_in[7 + 4 * i];
        gL[i]  = (const float*)d_in[8 + 4 * i];
        beL[i] = (const float*)d_in[9 + 4 * i];
    }
    const float* w5 = (const float*)d_in[22];
    const float* b5 = (const float*)d_in[23];
    float* out = (float*)d_out;

    float *bufA, *bufB, *bufC, *stats, *nptr;
    cudaGetSymbolAddress((void**)&bufA,  g_bufA);
    cudaGetSymbolAddress((void**)&bufB,  g_bufB);
    cudaGetSymbolAddress((void**)&bufC,  g_bufC);
    cudaGetSymbolAddress((void**)&stats, g_stats);
    cudaGetSymbolAddress((void**)&nptr,  g_n);

    k_zero<<<1, 192>>>(stats, nptr);
    // layer 0 + maskf output (y occupies first 16*NV floats of d_out)
    k_layer0<<<2048, 256>>>(feat, mask, w0, b0, bufA, out + 16 * NV, stats, nptr);

    const dim3 grid(8, 16, 32);
    float* pin = bufA;
    float* pout = bufB;
    for (int l = 0; l < 4; l++) {
        const float* gprev  = (l == 0) ? g0  : gL[l - 1];
        const float* beprev = (l == 0) ? be0 : beL[l - 1];
        k_bnact<<<2048, 256>>>(pin, mask, gprev, beprev,
                               stats + 32 * l, nptr, bufC);
        k_conv3<<<grid, 256>>>(bufC, pout, mask, wL[l], bL[l],
                               stats + 32 * (l + 1));
        float* t = pin; pin = pout; pout = t;
    }
    k_layer5<<<2048, 256>>>(pin, mask, w5, b5, gL[3], beL[3],
                            stats + 32 * 4, nptr, out);
}

// round 16
// speedup vs baseline: 1.3933x; 1.0022x over previous
#include <cuda_runtime.h>

#define NV (128*128*128)          // 2097152 voxels
#define SLOPE 0.01f
#define EPSBN 1e-5f

// ---------------- persistent device scratch (no allocations allowed) --------
__device__ float g_bufA[16 * NV];   // 128 MB raw ping
__device__ float g_bufB[16 * NV];   // 128 MB raw pong
__device__ float g_bufC[16 * NV];   // 128 MB activated input
__device__ float g_stats[5 * 32];   // per layer: [0..15]=sum, [16..31]=sumsq
__device__ float g_n;               // active voxel count

// ---------------- f32x2 helpers (SASS FFMA2 path) ---------------------------
typedef unsigned long long u64;

__device__ __forceinline__ u64 fpack(float lo, float hi) {
    u64 d; asm("mov.b64 %0, {%1, %2};" : "=l"(d) : "f"(lo), "f"(hi)); return d;
}
__device__ __forceinline__ void funpack(u64 d, float& lo, float& hi) {
    asm("mov.b64 {%0, %1}, %2;" : "=f"(lo), "=f"(hi) : "l"(d));
}
__device__ __forceinline__ u64 ffma2(u64 a, u64 b, u64 c) {
    u64 d; asm("fma.rn.f32x2 %0, %1, %2, %3;" : "=l"(d) : "l"(a), "l"(b), "l"(c)); return d;
}
__device__ __forceinline__ unsigned smaddr(const void* p) {
    return (unsigned)__cvta_generic_to_shared(p);
}
__device__ __forceinline__ void cpa4(unsigned dst, const void* src, unsigned sz) {
    asm volatile("cp.async.ca.shared.global [%0], [%1], 4, %2;"
                 :: "r"(dst), "l"(src), "r"(sz));
}

// ---------------- stats zeroing ---------------------------------------------
__global__ void k_zero(float* __restrict__ stats, float* __restrict__ nptr) {
    int t = threadIdx.x;
    if (t < 160) stats[t] = 0.f;
    if (t == 160) *nptr = 0.f;
}

// ---------------- layer 0: 1x1 conv 4->16, masked, + stats + maskf out ------
__global__ __launch_bounds__(256)
void k_layer0(const float* __restrict__ feat, const int* __restrict__ mask,
              const float* __restrict__ w0, const float* __restrict__ b0,
              float* __restrict__ outA, float* __restrict__ maskOut,
              float* __restrict__ statsOut, float* __restrict__ nOut)
{
    __shared__ float ws[64];   // ws[ci*16+co]
    __shared__ float bs[16];
    __shared__ float red[33];
    const int tid = threadIdx.x;
    if (tid < 64) { int co = tid >> 2, ci = tid & 3; ws[ci * 16 + co] = w0[co * 4 + ci]; }
    if (tid < 16) bs[tid] = b0[tid];
    if (tid < 33) red[tid] = 0.f;
    __syncthreads();

    const int v = (blockIdx.x * 256 + tid) * 4;
    const int4 m4 = *(const int4*)(mask + v);
    const float4 mf = make_float4(m4.x > 0 ? 1.f : 0.f, m4.y > 0 ? 1.f : 0.f,
                                  m4.z > 0 ? 1.f : 0.f, m4.w > 0 ? 1.f : 0.f);
    *(float4*)(maskOut + v) = mf;

    float4 acc[16];
    #pragma unroll
    for (int co = 0; co < 16; co++) acc[co] = make_float4(bs[co], bs[co], bs[co], bs[co]);
    #pragma unroll
    for (int ci = 0; ci < 4; ci++) {
        const float4 x = *(const float4*)(feat + ci * NV + v);
        #pragma unroll
        for (int co = 0; co < 16; co++) {
            const float wv = ws[ci * 16 + co];
            acc[co].x += wv * x.x; acc[co].y += wv * x.y;
            acc[co].z += wv * x.z; acc[co].w += wv * x.w;
        }
    }
    float s[16], q[16];
    #pragma unroll
    for (int co = 0; co < 16; co++) {
        const float4 o = make_float4(acc[co].x * mf.x, acc[co].y * mf.y,
                                     acc[co].z * mf.z, acc[co].w * mf.w);
        *(float4*)(outA + co * NV + v) = o;
        s[co] = o.x + o.y + o.z + o.w;
        q[co] = o.x * o.x + o.y * o.y + o.z * o.z + o.w * o.w;
    }
    float cnt = mf.x + mf.y + mf.z + mf.w;
    #pragma unroll
    for (int off = 16; off; off >>= 1) {
        cnt += __shfl_xor_sync(0xffffffffu, cnt, off);
        #pragma unroll
        for (int co = 0; co < 16; co++) {
            s[co] += __shfl_xor_sync(0xffffffffu, s[co], off);
            q[co] += __shfl_xor_sync(0xffffffffu, q[co], off);
        }
    }
    if ((tid & 31) == 0) {
        #pragma unroll
        for (int co = 0; co < 16; co++) {
            atomicAdd(&red[co], s[co]);
            atomicAdd(&red[16 + co], q[co]);
        }
        atomicAdd(&red[32], cnt);
    }
    __syncthreads();
    if (tid < 32) atomicAdd(&statsOut[tid], red[tid]);
    if (tid == 32) atomicAdd(nOut, red[32]);
}

// ---------------- BN + LeakyReLU pass: raw -> activated (masked) ------------
__global__ __launch_bounds__(256)
void k_bnact(const float* __restrict__ raw, const int* __restrict__ mask,
             const float* __restrict__ gam, const float* __restrict__ bet,
             const float* __restrict__ statsIn, const float* __restrict__ nPtr,
             float* __restrict__ act)
{
    __shared__ float s_sc[16], s_sh[16];
    const int tid = threadIdx.x;
    if (tid < 16) {
        const float n    = *nPtr;
        const float mean = statsIn[tid] / n;
        const float var  = statsIn[16 + tid] / n - mean * mean;
        const float inv  = rsqrtf(var + EPSBN);
        const float sc   = gam[tid] * inv;
        s_sc[tid] = sc;
        s_sh[tid] = bet[tid] - mean * sc;
    }
    __syncthreads();

    const int v = (blockIdx.x * 256 + tid) * 4;
    const int4 m4 = *(const int4*)(mask + v);
    const float4 mf = make_float4(m4.x > 0 ? 1.f : 0.f, m4.y > 0 ? 1.f : 0.f,
                                  m4.z > 0 ? 1.f : 0.f, m4.w > 0 ? 1.f : 0.f);
    #pragma unroll
    for (int ci = 0; ci < 16; ci++) {
        const float4 a = *(const float4*)(raw + ci * NV + v);
        const float sc = s_sc[ci], sh = s_sh[ci];
        float4 t;
        t.x = sc * a.x + sh; t.y = sc * a.y + sh;
        t.z = sc * a.z + sh; t.w = sc * a.w + sh;
        t.x = ((t.x >= 0.f) ? t.x : SLOPE * t.x) * mf.x;
        t.y = ((t.y >= 0.f) ? t.y : SLOPE * t.y) * mf.y;
        t.z = ((t.z >= 0.f) ? t.z : SLOPE * t.z) * mf.z;
        t.w = ((t.w >= 0.f) ? t.w : SLOPE * t.w) * mf.w;
        *(float4*)(act + ci * NV + v) = t;
    }
}

// ---------------- 3x3x3 subm conv 16->16 on preactivated input --------------
// block: 256 threads; output tile 16(X) x 8(Y) x 4(Z); each thread:
//   8 output channels as 4 f32x2 co-pairs x 4 voxels along X
// cp.async double-buffered fills; weights fetched as LDS.128 broadcasts
__global__ __launch_bounds__(256, 3)
void k_conv3(const float* __restrict__ act, float* __restrict__ outBuf,
             const int* __restrict__ mask,
             const float* __restrict__ w, const float* __restrict__ bias,
             float* __restrict__ statsOut)
{
    __shared__ __align__(16) float s_in[2][4320];  // [buf][ci4:4][z:6][y:10][x:18]
    __shared__ __align__(16) float s_w[2][1728];   // [buf][(cl*27 + tap)*16 + co]
    __shared__ float s_red[32];
    __shared__ float s_b[16];

    const int tid = threadIdx.x;
    if (tid < 32) s_red[tid] = 0.f;
    if (tid < 16) s_b[tid] = bias[tid];

    const int tx  = tid & 3;
    const int ty  = (tid >> 2) & 7;
    const int tz  = (tid >> 5) & 3;
    const int cog = tid >> 7;
    const int X0 = blockIdx.x * 16, Y0 = blockIdx.y * 8, Z0 = blockIdx.z * 4;

    auto fill = [&](int cc, int b) {
        // input tile (halo, zero-filled out of range; act already has BN+LReLU+mask)
        for (int i = tid; i < 4320; i += 256) {
            const int cl = i / 1080;
            const int r  = i - cl * 1080;
            const int z  = r / 180;
            const int r2 = r - z * 180;
            const int y  = r2 / 18;
            const int x  = r2 - y * 18;
            const int gz = Z0 + z - 1, gy = Y0 + y - 1, gx = X0 + x - 1;
            const bool ok = ((unsigned)gz < 128u) & ((unsigned)gy < 128u) & ((unsigned)gx < 128u);
            const int gv = ok ? ((gz * 128 + gy) * 128 + gx) : 0;
            const float* src = ok ? (act + (cc * 4 + cl) * NV + gv) : act;
            cpa4(smaddr(&s_in[b][i]), src, ok ? 4u : 0u);
        }
        // weights for this chunk, transposed so co is innermost
        for (int i = tid; i < 1728; i += 256) {
            const int cl = i / 432;
            const int r  = i - cl * 432;
            const int t  = r >> 4;
            const int co = r & 15;
            cpa4(smaddr(&s_w[b][i]), w + (co * 16 + cc * 4 + cl) * 27 + t, 4u);
        }
        asm volatile("cp.async.commit_group;" ::: "memory");
    };

    u64 acc[4][4];    // [co_pair][voxel_x]
    #pragma unroll
    for (int p = 0; p < 4; p++)
        #pragma unroll
        for (int j = 0; j < 4; j++) acc[p][j] = 0ull;

    fill(0, 0);

    #pragma unroll 1
    for (int cc = 0; cc < 4; cc++) {        // 4 input-channel chunks of 4
        const int b = cc & 1;
        if (cc < 3) {
            fill(cc + 1, b ^ 1);
            asm volatile("cp.async.wait_group 1;" ::: "memory");
        } else {
            asm volatile("cp.async.wait_group 0;" ::: "memory");
        }
        __syncthreads();

        #pragma unroll 1
        for (int cl = 0; cl < 4; cl++) {
            const float* wci = s_w[b] + cl * 432 + cog * 8;
            #pragma unroll
            for (int kz = 0; kz < 3; kz++) {
                #pragma unroll
                for (int ky = 0; ky < 3; ky++) {
                    const float* rowp = s_in[b] +
                        ((cl * 6 + tz + kz) * 10 + ty + ky) * 18 + tx * 4;
                    const float2 v0 = ((const float2*)rowp)[0];
                    const float2 v1 = ((const float2*)rowp)[1];
                    const float2 v2 = ((const float2*)rowp)[2];
                    u64 dup[6];
                    dup[0] = fpack(v0.x, v0.x); dup[1] = fpack(v0.y, v0.y);
                    dup[2] = fpack(v1.x, v1.x); dup[3] = fpack(v1.y, v1.y);
                    dup[4] = fpack(v2.x, v2.x); dup[5] = fpack(v2.y, v2.y);
                    const float* wrow = wci + (kz * 3 + ky) * 48;
                    #pragma unroll
                    for (int kx = 0; kx < 3; kx++) {
                        // 8 consecutive aligned floats = 4 co-pair weights:
                        // two LDS.128 broadcasts instead of four LDS.64
                        const ulonglong2 wv0 = *(const ulonglong2*)(wrow + kx * 16);
                        const ulonglong2 wv1 = *(const ulonglong2*)(wrow + kx * 16 + 4);
                        const u64 wp0 = wv0.x, wp1 = wv0.y, wp2 = wv1.x, wp3 = wv1.y;
                        #pragma unroll
                        for (int j = 0; j < 4; j++) {
                            acc[0][j] = ffma2(dup[j + kx], wp0, acc[0][j]);
                            acc[1][j] = ffma2(dup[j + kx], wp1, acc[1][j]);
                            acc[2][j] = ffma2(dup[j + kx], wp2, acc[2][j]);
                            acc[3][j] = ffma2(dup[j + kx], wp3, acc[3][j]);
                        }
                    }
                }
            }
        }
        __syncthreads();
    }

    // ---- epilogue: bias, mask, store raw, accumulate this layer's stats ----
    const int oz = Z0 + tz, oy = Y0 + ty, ox = X0 + tx * 4;
    const int base = (oz * 128 + oy) * 128 + ox;
    const int4 m4 = *(const int4*)(mask + base);
    const float mm[4] = { m4.x > 0 ? 1.f : 0.f, m4.y > 0 ? 1.f : 0.f,
                          m4.z > 0 ? 1.f : 0.f, m4.w > 0 ? 1.f : 0.f };
    float o[8][4];
    #pragma unroll
    for (int p = 0; p < 4; p++)
        #pragma unroll
        for (int j = 0; j < 4; j++)
            funpack(acc[p][j], o[2 * p][j], o[2 * p + 1][j]);

    float ssum[8], ssq[8];
    #pragma unroll
    for (int co = 0; co < 8; co++) {
        const int c = cog * 8 + co;
        const float bb = s_b[c];
        float s = 0.f, q = 0.f;
        #pragma unroll
        for (int j = 0; j < 4; j++) {
            const float val = (o[co][j] + bb) * mm[j];
            o[co][j] = val; s += val; q += val * val;
        }
        *(float4*)(outBuf + c * NV + base) =
            make_float4(o[co][0], o[co][1], o[co][2], o[co][3]);
        ssum[co] = s; ssq[co] = q;
    }
    #pragma unroll
    for (int off = 16; off; off >>= 1) {
        #pragma unroll
        for (int co = 0; co < 8; co++) {
            ssum[co] += __shfl_xor_sync(0xffffffffu, ssum[co], off);
            ssq[co]  += __shfl_xor_sync(0xffffffffu, ssq[co],  off);
        }
    }
    if ((tid & 31) == 0) {
        #pragma unroll
        for (int co = 0; co < 8; co++) {
            const int c = cog * 8 + co;
            atomicAdd(&s_red[c], ssum[co]);
            atomicAdd(&s_red[16 + c], ssq[co]);
        }
    }
    __syncthreads();
    if (tid < 32) atomicAdd(&statsOut[tid], s_red[tid]);
}

// ---------------- layer 5: BN4+act then 1x1 conv 16->16, masked, to d_out ---
__global__ __launch_bounds__(256)
void k_layer5(const float* __restrict__ inBuf, const int* __restrict__ mask,
              const float* __restrict__ w5, const float* __restrict__ b5,
              const float* __restrict__ gam, const float* __restrict__ bet,
              const float* __restrict__ statsIn, const float* __restrict__ nPtr,
              float* __restrict__ out)
{
    __shared__ float ws[256];                 // ws[ci*16+co]
    __shared__ float s_sc[16], s_sh[16], s_b[16];
    const int tid = threadIdx.x;
    { const int ci = tid >> 4, co = tid & 15; ws[tid] = w5[co * 16 + ci]; }
    if (tid < 16) {
        const float n    = *nPtr;
        const float mean = statsIn[tid] / n;
        const float var  = statsIn[16 + tid] / n - mean * mean;
        const float inv  = rsqrtf(var + EPSBN);
        const float sc   = gam[tid] * inv;
        s_sc[tid] = sc;
        s_sh[tid] = bet[tid] - mean * sc;
        s_b[tid]  = b5[tid];
    }
    __syncthreads();

    const int v = (blockIdx.x * 256 + tid) * 4;
    const int4 m4 = *(const int4*)(mask + v);
    const float4 mf = make_float4(m4.x > 0 ? 1.f : 0.f, m4.y > 0 ? 1.f : 0.f,
                                  m4.z > 0 ? 1.f : 0.f, m4.w > 0 ? 1.f : 0.f);
    float4 acc[16];
    #pragma unroll
    for (int co = 0; co < 16; co++) acc[co] = make_float4(0.f, 0.f, 0.f, 0.f);
    #pragma unroll
    for (int ci = 0; ci < 16; ci++) {
        const float4 a = *(const float4*)(inBuf + ci * NV + v);
        const float sc = s_sc[ci], sh = s_sh[ci];
        float4 t;
        t.x = sc * a.x + sh; t.y = sc * a.y + sh;
        t.z = sc * a.z + sh; t.w = sc * a.w + sh;
        t.x = ((t.x >= 0.f) ? t.x : SLOPE * t.x) * mf.x;
        t.y = ((t.y >= 0.f) ? t.y : SLOPE * t.y) * mf.y;
        t.z = ((t.z >= 0.f) ? t.z : SLOPE * t.z) * mf.z;
        t.w = ((t.w >= 0.f) ? t.w : SLOPE * t.w) * mf.w;
        #pragma unroll
        for (int co = 0; co < 16; co++) {
            const float wv = ws[ci * 16 + co];
            acc[co].x += wv * t.x; acc[co].y += wv * t.y;
            acc[co].z += wv * t.z; acc[co].w += wv * t.w;
        }
    }
    #pragma unroll
    for (int co = 0; co < 16; co++) {
        const float bb = s_b[co];
        const float4 o = make_float4((acc[co].x + bb) * mf.x, (acc[co].y + bb) * mf.y,
                                     (acc[co].z + bb) * mf.z, (acc[co].w + bb) * mf.w);
        *(float4*)(out + co * NV + v) = o;
    }
}

// ---------------- host launcher ---------------------------------------------
extern "C" void kernel_launch(void* const* d_in, const int* in_sizes, int n_in,
                              void* d_out, int out_size)
{
    (void)in_sizes; (void)n_in; (void)out_size;
    const float* feat = (const float*)d_in[0];
    const int*   mask = (const int*)d_in[1];
    const float* w0  = (const float*)d_in[2];
    const float* b0  = (const float*)d_in[3];
    const float* g0  = (const float*)d_in[4];
    const float* be0 = (const float*)d_in[5];
    const float *wL[4], *bL[4], *gL[4], *beL[4];
    for (int i = 0; i < 4; i++) {
        wL[i]  = (const float*)d_in[6 + 4 * i];
        bL[i]  = (const float*)d_in[7 + 4 * i];
        gL[i]  = (const float*)d_in[8 + 4 * i];
        beL[i] = (const float*)d_in[9 + 4 * i];
    }
    const float* w5 = (const float*)d_in[22];
    const float* b5 = (const float*)d_in[23];
    float* out = (float*)d_out;

    float *bufA, *bufB, *bufC, *stats, *nptr;
    cudaGetSymbolAddress((void**)&bufA,  g_bufA);
    cudaGetSymbolAddress((void**)&bufB,  g_bufB);
    cudaGetSymbolAddress((void**)&bufC,  g_bufC);
    cudaGetSymbolAddress((void**)&stats, g_stats);
    cudaGetSymbolAddress((void**)&nptr,  g_n);

    k_zero<<<1, 192>>>(stats, nptr);
    // layer 0 + maskf output (y occupies first 16*NV floats of d_out)
    k_layer0<<<2048, 256>>>(feat, mask, w0, b0, bufA, out + 16 * NV, stats, nptr);

    const dim3 grid(8, 16, 32);
    float* pin = bufA;
    float* pout = bufB;
    for (int l = 0; l < 4; l++) {
        const float* gprev  = (l == 0) ? g0  : gL[l - 1];
        const float* beprev = (l == 0) ? be0 : beL[l - 1];
        k_bnact<<<2048, 256>>>(pin, mask, gprev, beprev,
                               stats + 32 * l, nptr, bufC);
        k_conv3<<<grid, 256>>>(bufC, pout, mask, wL[l], bL[l],
                               stats + 32 * (l + 1));
        float* t = pin; pin = pout; pout = t;
    }
    k_layer5<<<2048, 256>>>(pin, mask, w5, b5, gL[3], beL[3],
                            stats + 32 * 4, nptr, out);
}